// round 1
// baseline (speedup 1.0000x reference)
#include <cuda_runtime.h>
#include <cstdint>
#include <cstddef>

// ---------------------------------------------------------------------------
// SO3Reparameterize: z = expmap(x@Wmu+bmu) @ expmap(L @ (sqrt(softplus(x@Wd+bd))*eps))
// Fused skinny GEMM (X[65536,1024] @ W9[1024,9]) + per-row epilogue.
// ---------------------------------------------------------------------------

#define K_DIM     1024
#define KC        32                  // k-chunk per pipeline stage
#define NCHUNK    (K_DIM / KC)        // 32
#define TILE_ROWS 256
#define THREADS   128                 // each thread owns 2 rows
#define PITCH     36                  // KC + 4 pad (floats) -> conflict-free LDS.128
#define WPACK_ELEMS ((K_DIM / 4) * 36) // kb-groups * (9 cols * 4 k) = 9216 floats

__device__ float g_wpack[WPACK_ELEMS];

// Pack Wmu|Wd|Wl ([1024,3] each) into wpack[kb][j][4]:
// for k-group kb (4 consecutive k), column j in 0..8, the 4 k-values contiguous.
__global__ void pack_w_kernel(const float* __restrict__ Wmu,
                              const float* __restrict__ Wd,
                              const float* __restrict__ Wl) {
    int idx = blockIdx.x * blockDim.x + threadIdx.x;
    if (idx >= WPACK_ELEMS) return;
    int kb  = idx / 36;
    int rem = idx - kb * 36;
    int j   = rem >> 2;
    int kk  = rem & 3;
    int k   = kb * 4 + kk;
    float v;
    if (j < 3)      v = Wmu[k * 3 + j];
    else if (j < 6) v = Wd [k * 3 + (j - 3)];
    else            v = Wl [k * 3 + (j - 6)];
    g_wpack[idx] = v;
}

// ---- packed f32x2 FMA helpers (sm_100+) -----------------------------------
__device__ __forceinline__ void ffma2(unsigned long long& acc,
                                      unsigned long long a,
                                      unsigned long long b) {
    asm("fma.rn.f32x2 %0, %1, %2, %0;" : "+l"(acc) : "l"(a), "l"(b));
}
__device__ __forceinline__ float2 unpack2(unsigned long long v) {
    float2 r;
    asm("mov.b64 {%0, %1}, %2;" : "=f"(r.x), "=f"(r.y) : "l"(v));
    return r;
}

__device__ __forceinline__ unsigned smem_u32(const void* p) {
    return (unsigned)__cvta_generic_to_shared(p);
}
__device__ __forceinline__ void cp_async16(unsigned dst, const void* src) {
    asm volatile("cp.async.cg.shared.global [%0], [%1], 16;" :: "r"(dst), "l"(src));
}

// ---- epilogue math ---------------------------------------------------------
__device__ __forceinline__ float softplus_f(float z) {
    return fmaxf(z, 0.0f) + log1pf(expf(-fabsf(z)));
}

__device__ __forceinline__ void rodrigues(float vx, float vy, float vz, float R[9]) {
    float th  = sqrtf(vx * vx + vy * vy + vz * vz);
    float inv = 1.0f / th;                 // reference also divides (NaN if 0)
    float kx = vx * inv, ky = vy * inv, kz = vz * inv;
    float s, c;
    sincosf(th, &s, &c);
    float ct = 1.0f - c;
    R[0] = c + ct * kx * kx;  R[1] = ct * kx * ky - s * kz;  R[2] = ct * kx * kz + s * ky;
    R[3] = ct * kx * ky + s * kz;  R[4] = c + ct * ky * ky;  R[5] = ct * ky * kz - s * kx;
    R[6] = ct * kx * kz - s * ky;  R[7] = ct * ky * kz + s * kx;  R[8] = c + ct * kz * kz;
}

__device__ __forceinline__ void row_epilogue(
    const float a[9], const float* __restrict__ eps, float* __restrict__ out,
    int grow, int B, int n,
    float bm0, float bm1, float bm2,
    float bd0, float bd1, float bd2,
    float bl0, float bl1, float bl2)
{
    float mu0 = a[0] + bm0, mu1 = a[1] + bm1, mu2 = a[2] + bm2;
    float s0 = sqrtf(softplus_f(a[3] + bd0));
    float s1 = sqrtf(softplus_f(a[4] + bd1));
    float s2 = sqrtf(softplus_f(a[5] + bd2));
    float L0 = a[6] + bl0, L1 = a[7] + bl1, L2 = a[8] + bl2;

    float Rm[9];
    rodrigues(mu0, mu1, mu2, Rm);

    for (int ni = 0; ni < n; ni++) {
        const float* e = eps + ((size_t)ni * B + grow) * 3;
        float t0 = s0 * e[0], t1 = s1 * e[1], t2 = s2 * e[2];
        float v0 = t0;
        float v1 = L0 * t0 + t1;
        float v2 = L1 * t0 + L2 * t1 + t2;
        float Rv[9];
        rodrigues(v0, v1, v2, Rv);
        float* o = out + ((size_t)ni * B + grow) * 9;
#pragma unroll
        for (int i = 0; i < 3; i++) {
#pragma unroll
            for (int j = 0; j < 3; j++) {
                o[i * 3 + j] = Rm[i * 3 + 0] * Rv[0 * 3 + j]
                             + Rm[i * 3 + 1] * Rv[1 * 3 + j]
                             + Rm[i * 3 + 2] * Rv[2 * 3 + j];
            }
        }
    }
}

// ---- main fused kernel -----------------------------------------------------
extern __shared__ float smem_dyn[];

__global__ __launch_bounds__(THREADS, 2)
void so3_kernel(const float* __restrict__ x,
                const float* __restrict__ eps,
                const float* __restrict__ bmu,
                const float* __restrict__ bd,
                const float* __restrict__ bl,
                float* __restrict__ out,
                int B, int n)
{
    float* ws = smem_dyn;                      // packed W: 9216 floats (36 KB)
    float* xs = smem_dyn + WPACK_ELEMS;        // 2 stages * 256 rows * PITCH

    const int tid   = threadIdx.x;
    const int tile0 = blockIdx.x * TILE_ROWS;

    // prefetch chunk c into stage (c&1) via cp.async (coalesced 128B per 8 threads)
    auto prefetch = [&](int c) {
        const int s  = c & 1;
        const int k0 = c * KC;
        unsigned sbase = smem_u32(xs + s * TILE_ROWS * PITCH);
#pragma unroll
        for (int m = 0; m < (TILE_ROWS * (KC / 4)) / THREADS; m++) {   // 16
            int idx = m * THREADS + tid;
            int row = idx >> 3;          // 8 float4 per row (KC=32)
            int c4  = idx & 7;
            const float* g = x + (size_t)(tile0 + row) * K_DIM + k0 + c4 * 4;
            cp_async16(sbase + (unsigned)(row * PITCH + c4 * 4) * 4, g);
        }
        asm volatile("cp.async.commit_group;");
    };

    prefetch(0);
    prefetch(1);

    // stage packed W into smem (reused by all 32 chunks)
    {
        const float4* src = reinterpret_cast<const float4*>(g_wpack);
        float4*       dst = reinterpret_cast<float4*>(ws);
        for (int i = tid; i < WPACK_ELEMS / 4; i += THREADS)
            dst[i] = src[i];
    }

    unsigned long long accA[9], accB[9];
#pragma unroll
    for (int j = 0; j < 9; j++) { accA[j] = 0ull; accB[j] = 0ull; }

    const int rA = tid;
    const int rB = tid + THREADS;

    for (int c = 0; c < NCHUNK; c++) {
        if (c + 1 < NCHUNK) asm volatile("cp.async.wait_group 1;");
        else                asm volatile("cp.async.wait_group 0;");
        __syncthreads();

        const float* xs0 = xs + (c & 1) * TILE_ROWS * PITCH;
        const float* wsc = ws + (c * (KC / 4)) * 36;

#pragma unroll
        for (int g = 0; g < KC / 4; g++) {
            const ulonglong2* wp =
                reinterpret_cast<const ulonglong2*>(wsc + g * 36);
            ulonglong2 xa = *reinterpret_cast<const ulonglong2*>(xs0 + rA * PITCH + g * 4);
            ulonglong2 xb = *reinterpret_cast<const ulonglong2*>(xs0 + rB * PITCH + g * 4);
#pragma unroll
            for (int j = 0; j < 9; j++) {
                ulonglong2 w = wp[j];        // (w_j(k0),w_j(k1)) | (w_j(k2),w_j(k3))
                ffma2(accA[j], xa.x, w.x);
                ffma2(accA[j], xa.y, w.y);
                ffma2(accB[j], xb.x, w.x);
                ffma2(accB[j], xb.y, w.y);
            }
        }
        __syncthreads();
        if (c + 2 < NCHUNK) prefetch(c + 2);
    }

    // reduce packed halves
    float a9[9], b9[9];
#pragma unroll
    for (int j = 0; j < 9; j++) {
        float2 ta = unpack2(accA[j]); a9[j] = ta.x + ta.y;
        float2 tb = unpack2(accB[j]); b9[j] = tb.x + tb.y;
    }

    float bm0 = bmu[0], bm1 = bmu[1], bm2 = bmu[2];
    float bd0 = bd[0],  bd1 = bd[1],  bd2 = bd[2];
    float bl0 = bl[0],  bl1 = bl[1],  bl2 = bl[2];

    row_epilogue(a9, eps, out, tile0 + rA, B, n, bm0, bm1, bm2, bd0, bd1, bd2, bl0, bl1, bl2);
    row_epilogue(b9, eps, out, tile0 + rB, B, n, bm0, bm1, bm2, bd0, bd1, bd2, bl0, bl1, bl2);
}

// ---------------------------------------------------------------------------
extern "C" void kernel_launch(void* const* d_in, const int* in_sizes, int n_in,
                              void* d_out, int out_size) {
    const float* x   = (const float*)d_in[0];
    const float* eps = (const float*)d_in[1];
    const float* Wmu = (const float*)d_in[2];
    const float* bmu = (const float*)d_in[3];
    const float* Wd  = (const float*)d_in[4];
    const float* bd  = (const float*)d_in[5];
    const float* Wl  = (const float*)d_in[6];
    const float* bl  = (const float*)d_in[7];
    float* out = (float*)d_out;

    const int K = in_sizes[2] / 3;          // 1024
    const int B = in_sizes[0] / K;          // 65536
    const int n = in_sizes[1] / (B * 3);    // 1

    pack_w_kernel<<<(WPACK_ELEMS + 255) / 256, 256>>>(Wmu, Wd, Wl);

    const size_t smem_bytes =
        (size_t)(WPACK_ELEMS + 2 * TILE_ROWS * PITCH) * sizeof(float); // 110,592 B
    cudaFuncSetAttribute(so3_kernel,
                         cudaFuncAttributeMaxDynamicSharedMemorySize,
                         (int)smem_bytes);

    so3_kernel<<<B / TILE_ROWS, THREADS, smem_bytes>>>(x, eps, bmu, bd, bl, out, B, n);
}